// round 9
// baseline (speedup 1.0000x reference)
#include <cuda_runtime.h>
#include <cuda_bf16.h>
#include <math.h>
#include <stdint.h>

// ---------------------------------------------------------------------------
// GIN 2-layer forward:
//   agg1 = x + segsum(x[src] -> dst)
//   h    = relu(agg1 @ W1a + b1a); x1 = relu(h @ W1b + b1b)
//   agg2 = x1 + segsum(x1[src] -> dst)
//   h2   = relu(agg2 @ W2a + b2a); out = softmax(h2 @ W2b + b2b)
//
// NOTE: device scratch lives in __device__ globals. Host code must NEVER pass
// the bare symbol as a kernel argument (on GB300/ATS that silently resolves to
// the host shadow!). All kernels take pointers obtained via
// cudaGetSymbolAddress, and no kernel references the symbols directly.
// ---------------------------------------------------------------------------

#define DIM 128
#define NCLS 40
#define MAX_NODES 100352   // 100000 rounded up to multiple of 128

__device__ float g_agg[(size_t)MAX_NODES * DIM];
__device__ float g_h  [(size_t)MAX_NODES * DIM];
__device__ float g_x1 [(size_t)MAX_NODES * DIM];

// ---------------------------------------------------------------------------
// init accumulator with x (fuses the "+ x" of GIN into the scatter target)
// ---------------------------------------------------------------------------
__global__ __launch_bounds__(256) void init_agg(float* __restrict__ dst,
                                                const float* __restrict__ src, int n4)
{
    int i = blockIdx.x * blockDim.x + threadIdx.x;
    if (i < n4)
        reinterpret_cast<float4*>(dst)[i] =
            reinterpret_cast<const float4*>(src)[i];
}

// ---------------------------------------------------------------------------
// scatter: one warp per edge. lane l handles elements l, l+32, l+64, l+96 of
// the 128-dim row -> every LDG and every RED instruction is a fully-coalesced
// 128B warp access. Plain atomicAdd for guaranteed semantics.
// ---------------------------------------------------------------------------
__global__ __launch_bounds__(256) void scatter_edges(float* __restrict__ agg,
                                                     const float* __restrict__ x,
                                                     const int* __restrict__ edges,
                                                     int n_edges)
{
    int gw   = (blockIdx.x * blockDim.x + threadIdx.x) >> 5;
    int lane = threadIdx.x & 31;
    if (gw >= n_edges) return;
    int2 e = __ldg(reinterpret_cast<const int2*>(edges) + gw);
    const float* __restrict__ xr = x + (size_t)e.x * DIM;
    float* __restrict__ ar = agg + (size_t)e.y * DIM;
    float v0 = __ldg(xr + lane);
    float v1 = __ldg(xr + lane + 32);
    float v2 = __ldg(xr + lane + 64);
    float v3 = __ldg(xr + lane + 96);
    atomicAdd(ar + lane,      v0);
    atomicAdd(ar + lane + 32, v1);
    atomicAdd(ar + lane + 64, v2);
    atomicAdd(ar + lane + 96, v3);
}

// ---------------------------------------------------------------------------
// SGEMM: C[M,128] = relu(A[M,128] @ W[128,128] + b)
// BM=128, BN=128, BK=16, 256 threads, 8x8 microtile per thread
// ---------------------------------------------------------------------------
__global__ __launch_bounds__(256) void sgemm128(const float* __restrict__ A,
                                                const float* __restrict__ W,
                                                const float* __restrict__ bias,
                                                float* __restrict__ C,
                                                int M)
{
    __shared__ float As[16][132];   // [k][m], padded for conflict-free transpose store
    __shared__ float Bs[16][128];   // [k][n]

    const int tid = threadIdx.x;
    const int tx  = tid & 15;       // n-group: cols tx*8 .. tx*8+7
    const int ty  = tid >> 4;       // m-group: rows ty*8 .. ty*8+7
    const int m0  = blockIdx.x * 128;

    float acc[8][8];
#pragma unroll
    for (int i = 0; i < 8; i++)
#pragma unroll
        for (int j = 0; j < 8; j++) acc[i][j] = 0.f;

    float bv[8];
#pragma unroll
    for (int j = 0; j < 8; j++) bv[j] = __ldg(&bias[tx * 8 + j]);

    for (int kc = 0; kc < 8; kc++) {
        const int k0 = kc * 16;
        // load A tile (transposed into As[k][m]); zero-fill out-of-range rows
#pragma unroll
        for (int h = 0; h < 2; h++) {
            int s = tid + 256 * h;          // 512 float4 slots
            int row = s >> 2, q = s & 3;
            int gm = m0 + row;
            float4 v = make_float4(0.f, 0.f, 0.f, 0.f);
            if (gm < M)
                v = *reinterpret_cast<const float4*>(&A[(size_t)gm * DIM + k0 + q * 4]);
            As[q * 4 + 0][row] = v.x;
            As[q * 4 + 1][row] = v.y;
            As[q * 4 + 2][row] = v.z;
            As[q * 4 + 3][row] = v.w;
        }
        // load W tile
#pragma unroll
        for (int h = 0; h < 2; h++) {
            int s = tid + 256 * h;          // 512 float4 slots
            int k = s >> 5, cq = s & 31;
            *reinterpret_cast<float4*>(&Bs[k][cq * 4]) =
                *reinterpret_cast<const float4*>(&W[(size_t)(k0 + k) * DIM + cq * 4]);
        }
        __syncthreads();

#pragma unroll
        for (int k = 0; k < 16; k++) {
            float a[8], b[8];
            *reinterpret_cast<float4*>(&a[0]) = *reinterpret_cast<float4*>(&As[k][ty * 8]);
            *reinterpret_cast<float4*>(&a[4]) = *reinterpret_cast<float4*>(&As[k][ty * 8 + 4]);
            *reinterpret_cast<float4*>(&b[0]) = *reinterpret_cast<float4*>(&Bs[k][tx * 8]);
            *reinterpret_cast<float4*>(&b[4]) = *reinterpret_cast<float4*>(&Bs[k][tx * 8 + 4]);
#pragma unroll
            for (int i = 0; i < 8; i++)
#pragma unroll
                for (int j = 0; j < 8; j++)
                    acc[i][j] = fmaf(a[i], b[j], acc[i][j]);
        }
        __syncthreads();
    }

    // epilogue: bias + relu + store
#pragma unroll
    for (int i = 0; i < 8; i++) {
        int gm = m0 + ty * 8 + i;
        if (gm < M) {
            float4 r0, r1;
            r0.x = fmaxf(acc[i][0] + bv[0], 0.f);
            r0.y = fmaxf(acc[i][1] + bv[1], 0.f);
            r0.z = fmaxf(acc[i][2] + bv[2], 0.f);
            r0.w = fmaxf(acc[i][3] + bv[3], 0.f);
            r1.x = fmaxf(acc[i][4] + bv[4], 0.f);
            r1.y = fmaxf(acc[i][5] + bv[5], 0.f);
            r1.z = fmaxf(acc[i][6] + bv[6], 0.f);
            r1.w = fmaxf(acc[i][7] + bv[7], 0.f);
            *reinterpret_cast<float4*>(&C[(size_t)gm * DIM + tx * 8 + 0]) = r0;
            *reinterpret_cast<float4*>(&C[(size_t)gm * DIM + tx * 8 + 4]) = r1;
        }
    }
}

// ---------------------------------------------------------------------------
// Fused layer-2 head per 128-node tile:
//   H2 = relu(A @ W2a + b2a)   (A = agg2, [128n x 128] @ [128 x 40])
//   O  = H2 @ W2b + b2b        ([128n x 40] @ [40 x 40])
//   out = softmax(O, axis=-1)
// All in <=48KB static smem via phase-overlaid regions.
// ---------------------------------------------------------------------------
__global__ __launch_bounds__(256) void layer2_head(const float* __restrict__ A,
                                                   const float* __restrict__ W2a,
                                                   const float* __restrict__ b2a,
                                                   const float* __restrict__ W2b,
                                                   const float* __restrict__ b2b,
                                                   float* __restrict__ out,
                                                   int M)
{
    __shared__ float sm[12176];                 // 48,704 bytes
    float* As   = sm;            // phase1: [128][36] A chunk         (4608)
    float* W2as = sm + 4608;     // phase1: [128][40] W2a             (5120) ends 9728
    float* H2s  = sm;            // phase2: [128][40]                 (5120)
    float* W2bs = sm + 5120;     // phase2: [40][40]                  (1600)
    float* Os   = sm + 6720;     // phase2: [128][40] logits          (5120) ends 11840
    float* b2as = sm + 11840;    // (40)
    float* b2bs = sm + 11880;    // (40)
    float* rmax = sm + 11920;    // (128)
    float* rinv = sm + 12048;    // (128)

    const int tid = threadIdx.x;
    const int m0  = blockIdx.x * 128;
    const int tmg = tid >> 3;    // 0..31  -> rows tmg*4 .. +3
    const int tjg = tid & 7;     // 0..7   -> cols tjg*5 .. +4

    // persistent loads
    for (int s = tid; s < 5120; s += 256) W2as[s] = W2a[s];
    if (tid < NCLS) { b2as[tid] = b2a[tid]; b2bs[tid] = b2b[tid]; }
    __syncthreads();

    // ---- phase 1: H2 = relu(A @ W2a + b2a), K chunked by 32 ----
    float acc[4][5];
#pragma unroll
    for (int mi = 0; mi < 4; mi++)
#pragma unroll
        for (int jj = 0; jj < 5; jj++) acc[mi][jj] = b2as[tjg * 5 + jj];

    for (int kc = 0; kc < 4; kc++) {
#pragma unroll
        for (int h = 0; h < 4; h++) {
            int s = tid + 256 * h;          // 1024 float4 slots
            int row = s >> 3, q = s & 7;
            int gm = m0 + row;
            float4 v = make_float4(0.f, 0.f, 0.f, 0.f);
            if (gm < M)
                v = *reinterpret_cast<const float4*>(&A[(size_t)gm * DIM + kc * 32 + q * 4]);
            *reinterpret_cast<float4*>(&As[row * 36 + q * 4]) = v;
        }
        __syncthreads();
#pragma unroll
        for (int k = 0; k < 32; k++) {
            float a[4], w[5];
#pragma unroll
            for (int mi = 0; mi < 4; mi++) a[mi] = As[(tmg * 4 + mi) * 36 + k];
#pragma unroll
            for (int jj = 0; jj < 5; jj++) w[jj] = W2as[(kc * 32 + k) * NCLS + tjg * 5 + jj];
#pragma unroll
            for (int mi = 0; mi < 4; mi++)
#pragma unroll
                for (int jj = 0; jj < 5; jj++)
                    acc[mi][jj] = fmaf(a[mi], w[jj], acc[mi][jj]);
        }
        __syncthreads();
    }

    // ---- transition: relu, write H2 to smem (overwrites As/W2as), load W2b ----
#pragma unroll
    for (int mi = 0; mi < 4; mi++)
#pragma unroll
        for (int jj = 0; jj < 5; jj++)
            H2s[(tmg * 4 + mi) * NCLS + tjg * 5 + jj] = fmaxf(acc[mi][jj], 0.f);
    for (int s = tid; s < 1600; s += 256) W2bs[s] = W2b[s];
    __syncthreads();

    // ---- phase 2: logits O = H2 @ W2b + b2b ----
    float acc2[4][5];
#pragma unroll
    for (int mi = 0; mi < 4; mi++)
#pragma unroll
        for (int jj = 0; jj < 5; jj++) acc2[mi][jj] = b2bs[tjg * 5 + jj];

#pragma unroll
    for (int k = 0; k < NCLS; k++) {
        float hreg[4], w[5];
#pragma unroll
        for (int mi = 0; mi < 4; mi++) hreg[mi] = H2s[(tmg * 4 + mi) * NCLS + k];
#pragma unroll
        for (int jj = 0; jj < 5; jj++) w[jj] = W2bs[k * NCLS + tjg * 5 + jj];
#pragma unroll
        for (int mi = 0; mi < 4; mi++)
#pragma unroll
            for (int jj = 0; jj < 5; jj++)
                acc2[mi][jj] = fmaf(hreg[mi], w[jj], acc2[mi][jj]);
    }
#pragma unroll
    for (int mi = 0; mi < 4; mi++)
#pragma unroll
        for (int jj = 0; jj < 5; jj++)
            Os[(tmg * 4 + mi) * NCLS + tjg * 5 + jj] = acc2[mi][jj];
    __syncthreads();

    // ---- softmax row stats: thread t handles row t ----
    if (tid < 128) {
        float mx = -INFINITY;
#pragma unroll
        for (int c = 0; c < NCLS; c++) mx = fmaxf(mx, Os[tid * NCLS + c]);
        float s = 0.f;
#pragma unroll
        for (int c = 0; c < NCLS; c++) s += __expf(Os[tid * NCLS + c] - mx);
        rmax[tid] = mx;
        rinv[tid] = 1.f / s;
    }
    __syncthreads();

    // ---- normalized store, coalesced ----
    int lim = (M - m0) * NCLS;
    if (lim > 128 * NCLS) lim = 128 * NCLS;
#pragma unroll
    for (int h = 0; h < 20; h++) {
        int e = tid + 256 * h;
        if (e < lim) {
            int m = e / NCLS;
            float v = __expf(Os[e] - rmax[m]) * rinv[m];
            out[(size_t)m0 * NCLS + e] = v;
        }
    }
}

// ---------------------------------------------------------------------------
// Identify inputs by element count (robust to metadata ordering). Within
// equal-size pairs (W1a/W1b, b1a/b1b, b2a/b2b), first occurrence = 'a'.
// ---------------------------------------------------------------------------
extern "C" void kernel_launch(void* const* d_in, const int* in_sizes, int n_in,
                              void* d_out, int out_size)
{
    const float* x   = 0; const int* edge = 0;
    const float* W1a = 0; const float* b1a = 0;
    const float* W1b = 0; const float* b1b = 0;
    const float* W2a = 0; const float* b2a = 0;
    const float* W2b = 0; const float* b2b = 0;
    int x_elems = 0, e_elems = 0;

    for (int i = 0; i < n_in; i++) {
        int sz = in_sizes[i];
        const void* p = d_in[i];
        if (sz >= 1000000 && sz % DIM == 0 && sz / DIM >= 50000) {
            if (!x) { x = (const float*)p; x_elems = sz; }
            else    { edge = (const int*)p; e_elems = sz; }     // shouldn't happen
        } else if (sz >= 1000000) {
            edge = (const int*)p; e_elems = sz;
        } else if (sz == DIM * DIM) {
            if (!W1a) W1a = (const float*)p; else W1b = (const float*)p;
        } else if (sz == DIM) {
            if (!b1a) b1a = (const float*)p; else b1b = (const float*)p;
        } else if (sz == DIM * NCLS) {
            W2a = (const float*)p;
        } else if (sz == NCLS * NCLS) {
            W2b = (const float*)p;
        } else if (sz == NCLS) {
            if (!b2a) b2a = (const float*)p; else b2b = (const float*)p;
        }
    }
    if (x && edge && e_elems > x_elems) {
        const void* tx = x; x = (const float*)edge; edge = (const int*)tx;
        int t = x_elems; x_elems = e_elems; e_elems = t;
    }

    // REAL device addresses of the scratch globals (host symbol name would be
    // the host shadow -> silently readable via ATS on GB300 = the round-3 bug).
    float *agg_p = 0, *h_p = 0, *x1_p = 0;
    cudaGetSymbolAddress((void**)&agg_p, g_agg);
    cudaGetSymbolAddress((void**)&h_p,   g_h);
    cudaGetSymbolAddress((void**)&x1_p,  g_x1);

    float* out = (float*)d_out;
    const int M = x_elems / DIM;              // 100000
    const int E = e_elems / 2;                // 1600000

    const int n4 = M * (DIM / 4);
    const int copy_blocks = (n4 + 255) / 256;
    const int scat_blocks = (E + 7) / 8;      // 8 warps (edges) per 256-thread block
    const int gemm_blocks = (M + 127) / 128;

    // layer 1
    init_agg<<<copy_blocks, 256>>>(agg_p, x, n4);
    scatter_edges<<<scat_blocks, 256>>>(agg_p, x, edge, E);
    sgemm128<<<gemm_blocks, 256>>>(agg_p, W1a, b1a, h_p, M);
    sgemm128<<<gemm_blocks, 256>>>(h_p, W1b, b1b, x1_p, M);

    // layer 2
    init_agg<<<copy_blocks, 256>>>(agg_p, x1_p, n4);
    scatter_edges<<<scat_blocks, 256>>>(agg_p, x1_p, edge, E);
    layer2_head<<<gemm_blocks, 256>>>(agg_p, W2a, b2a, W2b, b2b, out, M);
}

// round 10
// speedup vs baseline: 1.2219x; 1.2219x over previous
#include <cuda_runtime.h>
#include <cuda_bf16.h>
#include <math.h>
#include <stdint.h>

// ---------------------------------------------------------------------------
// GIN 2-layer forward (layer-2 scatter reordered through GEMM linearity):
//   agg1 = x + segsum(x[src]->dst)
//   h    = relu(agg1 @ W1a + b1a); x1 = relu(h @ W1b + b1b)
//   y    = x1 @ W2a                       (project to 40 dims FIRST)
//   agg40= y + segsum(y[src]->dst)        (scatter 40 dims, 3.2x less traffic)
//   h2   = relu(agg40 + b2a); out = softmax(h2 @ W2b + b2b)
//
// Scratch: __device__ globals; host passes cudaGetSymbolAddress pointers
// (bare symbols in host code resolve to the ATS-readable host shadow on GB300
// — the silent-corruption bug found in round 8).
// ---------------------------------------------------------------------------

#define DIM 128
#define NCLS 40
#define MAX_NODES 100352

__device__ float g_agg[(size_t)MAX_NODES * DIM];   // agg1; later reused: agg40
__device__ float g_h  [(size_t)MAX_NODES * DIM];   // h;    later reused: y40
__device__ float g_x1 [(size_t)MAX_NODES * DIM];   // x1

// ---------------------------------------------------------------------------
__global__ __launch_bounds__(256) void init_agg(float* __restrict__ dst,
                                                const float* __restrict__ src, int n4)
{
    int i = blockIdx.x * blockDim.x + threadIdx.x;
    if (i < n4)
        reinterpret_cast<float4*>(dst)[i] =
            reinterpret_cast<const float4*>(src)[i];
}

// ---------------------------------------------------------------------------
// layer-1 scatter: one warp per edge, lane l owns float4 chunk l of the row.
// Vectorized RED: 1 instruction per 16B, fully-coalesced 512B warp accesses.
// ---------------------------------------------------------------------------
__global__ __launch_bounds__(256) void scatter_edges(float* __restrict__ agg,
                                                     const float* __restrict__ x,
                                                     const int* __restrict__ edges,
                                                     int n_edges)
{
    int gw   = (blockIdx.x * blockDim.x + threadIdx.x) >> 5;
    int lane = threadIdx.x & 31;
    if (gw >= n_edges) return;
    int2 e = __ldg(reinterpret_cast<const int2*>(edges) + gw);
    const float4 v = reinterpret_cast<const float4*>(x + (size_t)e.x * DIM)[lane];
    float4* p = reinterpret_cast<float4*>(agg + (size_t)e.y * DIM) + lane;
    asm volatile("red.global.add.v4.f32 [%0], {%1,%2,%3,%4};"
                 :: "l"(p), "f"(v.x), "f"(v.y), "f"(v.z), "f"(v.w)
                 : "memory");
}

// ---------------------------------------------------------------------------
// layer-2 scatter in 40-dim space: thread t -> edge t/10, float4 chunk t%10.
// Rows are 160B (16B-aligned chunks), 10 chunks cover all 40 floats.
// ---------------------------------------------------------------------------
__global__ __launch_bounds__(256) void scatter40(float* __restrict__ agg,
                                                 const float* __restrict__ y,
                                                 const int* __restrict__ edges,
                                                 int n_edges)
{
    int idx = blockIdx.x * blockDim.x + threadIdx.x;
    if (idx >= n_edges * 10) return;
    int e = idx / 10;
    int c = idx - e * 10;
    int2 ed = __ldg(reinterpret_cast<const int2*>(edges) + e);
    const float4 v = reinterpret_cast<const float4*>(y + (size_t)ed.x * NCLS)[c];
    float4* p = reinterpret_cast<float4*>(agg + (size_t)ed.y * NCLS) + c;
    asm volatile("red.global.add.v4.f32 [%0], {%1,%2,%3,%4};"
                 :: "l"(p), "f"(v.x), "f"(v.y), "f"(v.z), "f"(v.w)
                 : "memory");
}

// ---------------------------------------------------------------------------
// SGEMM: C[M,128] = relu(A[M,128] @ W[128,128] + b)   (unchanged, known-good)
// ---------------------------------------------------------------------------
__global__ __launch_bounds__(256) void sgemm128(const float* __restrict__ A,
                                                const float* __restrict__ W,
                                                const float* __restrict__ bias,
                                                float* __restrict__ C,
                                                int M)
{
    __shared__ float As[16][132];
    __shared__ float Bs[16][128];

    const int tid = threadIdx.x;
    const int tx  = tid & 15;
    const int ty  = tid >> 4;
    const int m0  = blockIdx.x * 128;

    float acc[8][8];
#pragma unroll
    for (int i = 0; i < 8; i++)
#pragma unroll
        for (int j = 0; j < 8; j++) acc[i][j] = 0.f;

    float bv[8];
#pragma unroll
    for (int j = 0; j < 8; j++) bv[j] = __ldg(&bias[tx * 8 + j]);

    for (int kc = 0; kc < 8; kc++) {
        const int k0 = kc * 16;
#pragma unroll
        for (int h = 0; h < 2; h++) {
            int s = tid + 256 * h;
            int row = s >> 2, q = s & 3;
            int gm = m0 + row;
            float4 v = make_float4(0.f, 0.f, 0.f, 0.f);
            if (gm < M)
                v = *reinterpret_cast<const float4*>(&A[(size_t)gm * DIM + k0 + q * 4]);
            As[q * 4 + 0][row] = v.x;
            As[q * 4 + 1][row] = v.y;
            As[q * 4 + 2][row] = v.z;
            As[q * 4 + 3][row] = v.w;
        }
#pragma unroll
        for (int h = 0; h < 2; h++) {
            int s = tid + 256 * h;
            int k = s >> 5, cq = s & 31;
            *reinterpret_cast<float4*>(&Bs[k][cq * 4]) =
                *reinterpret_cast<const float4*>(&W[(size_t)(k0 + k) * DIM + cq * 4]);
        }
        __syncthreads();

#pragma unroll
        for (int k = 0; k < 16; k++) {
            float a[8], b[8];
            *reinterpret_cast<float4*>(&a[0]) = *reinterpret_cast<float4*>(&As[k][ty * 8]);
            *reinterpret_cast<float4*>(&a[4]) = *reinterpret_cast<float4*>(&As[k][ty * 8 + 4]);
            *reinterpret_cast<float4*>(&b[0]) = *reinterpret_cast<float4*>(&Bs[k][tx * 8]);
            *reinterpret_cast<float4*>(&b[4]) = *reinterpret_cast<float4*>(&Bs[k][tx * 8 + 4]);
#pragma unroll
            for (int i = 0; i < 8; i++)
#pragma unroll
                for (int j = 0; j < 8; j++)
                    acc[i][j] = fmaf(a[i], b[j], acc[i][j]);
        }
        __syncthreads();
    }

#pragma unroll
    for (int i = 0; i < 8; i++) {
        int gm = m0 + ty * 8 + i;
        if (gm < M) {
            float4 r0, r1;
            r0.x = fmaxf(acc[i][0] + bv[0], 0.f);
            r0.y = fmaxf(acc[i][1] + bv[1], 0.f);
            r0.z = fmaxf(acc[i][2] + bv[2], 0.f);
            r0.w = fmaxf(acc[i][3] + bv[3], 0.f);
            r1.x = fmaxf(acc[i][4] + bv[4], 0.f);
            r1.y = fmaxf(acc[i][5] + bv[5], 0.f);
            r1.z = fmaxf(acc[i][6] + bv[6], 0.f);
            r1.w = fmaxf(acc[i][7] + bv[7], 0.f);
            *reinterpret_cast<float4*>(&C[(size_t)gm * DIM + tx * 8 + 0]) = r0;
            *reinterpret_cast<float4*>(&C[(size_t)gm * DIM + tx * 8 + 4]) = r1;
        }
    }
}

// ---------------------------------------------------------------------------
// y[M,40] = A[M,128] @ W[128,40]  (no bias). Writes result to y AND agg
// (agg is the layer-2 accumulator init; fuses the old init_agg copy).
// ---------------------------------------------------------------------------
__global__ __launch_bounds__(256) void gemm_y40(const float* __restrict__ A,
                                                const float* __restrict__ W,
                                                float* __restrict__ y,
                                                float* __restrict__ agg,
                                                int M)
{
    __shared__ float As[128 * 36];     // [row][36] chunk of 32 K-cols, padded
    __shared__ float Ws[128 * NCLS];   // full W2a

    const int tid = threadIdx.x;
    const int m0  = blockIdx.x * 128;
    const int tmg = tid >> 3;    // rows tmg*4 .. +3
    const int tjg = tid & 7;     // cols tjg*5 .. +4

    for (int s = tid; s < 128 * NCLS; s += 256) Ws[s] = W[s];

    float acc[4][5];
#pragma unroll
    for (int mi = 0; mi < 4; mi++)
#pragma unroll
        for (int jj = 0; jj < 5; jj++) acc[mi][jj] = 0.f;

    for (int kc = 0; kc < 4; kc++) {
#pragma unroll
        for (int h = 0; h < 4; h++) {
            int s = tid + 256 * h;          // 1024 float4 slots
            int row = s >> 3, q = s & 7;
            int gm = m0 + row;
            float4 v = make_float4(0.f, 0.f, 0.f, 0.f);
            if (gm < M)
                v = *reinterpret_cast<const float4*>(&A[(size_t)gm * DIM + kc * 32 + q * 4]);
            *reinterpret_cast<float4*>(&As[row * 36 + q * 4]) = v;
        }
        __syncthreads();
#pragma unroll
        for (int k = 0; k < 32; k++) {
            float a[4], w[5];
#pragma unroll
            for (int mi = 0; mi < 4; mi++) a[mi] = As[(tmg * 4 + mi) * 36 + k];
#pragma unroll
            for (int jj = 0; jj < 5; jj++) w[jj] = Ws[(kc * 32 + k) * NCLS + tjg * 5 + jj];
#pragma unroll
            for (int mi = 0; mi < 4; mi++)
#pragma unroll
                for (int jj = 0; jj < 5; jj++)
                    acc[mi][jj] = fmaf(a[mi], w[jj], acc[mi][jj]);
        }
        __syncthreads();
    }

#pragma unroll
    for (int mi = 0; mi < 4; mi++) {
        int gm = m0 + tmg * 4 + mi;
        if (gm < M) {
#pragma unroll
            for (int jj = 0; jj < 5; jj++) {
                size_t idx = (size_t)gm * NCLS + tjg * 5 + jj;
                float v = acc[mi][jj];
                y[idx]   = v;
                agg[idx] = v;
            }
        }
    }
}

// ---------------------------------------------------------------------------
// head: per 128-row tile: H2 = relu(agg40 + b2a); O = H2 @ W2b + b2b;
// out = softmax(O). All smem.
// ---------------------------------------------------------------------------
__global__ __launch_bounds__(256) void head40(const float* __restrict__ agg,
                                              const float* __restrict__ b2a,
                                              const float* __restrict__ W2b,
                                              const float* __restrict__ b2b,
                                              float* __restrict__ out,
                                              int M)
{
    __shared__ float H2s[128 * NCLS];       // 5120
    __shared__ float W2bs[NCLS * NCLS];     // 1600
    __shared__ float Os[128 * NCLS];        // 5120
    __shared__ float b2as[NCLS], b2bs[NCLS];
    __shared__ float rmax[128], rinv[128];

    const int tid = threadIdx.x;
    const int m0  = blockIdx.x * 128;
    const int tmg = tid >> 3;
    const int tjg = tid & 7;

    for (int s = tid; s < NCLS * NCLS; s += 256) W2bs[s] = W2b[s];
    if (tid < NCLS) { b2as[tid] = b2a[tid]; b2bs[tid] = b2b[tid]; }
    __syncthreads();

    int lim = (M - m0) * NCLS;
    if (lim > 128 * NCLS) lim = 128 * NCLS;

    // tile load + bias + relu (zero-fill out-of-range rows)
#pragma unroll
    for (int h = 0; h < 20; h++) {
        int e = tid + 256 * h;
        float v = 0.f;
        if (e < lim) {
            int c = e % NCLS;
            v = fmaxf(agg[(size_t)m0 * NCLS + e] + b2as[c], 0.f);
        }
        H2s[e] = v;
    }
    __syncthreads();

    // logits
    float acc[4][5];
#pragma unroll
    for (int mi = 0; mi < 4; mi++)
#pragma unroll
        for (int jj = 0; jj < 5; jj++) acc[mi][jj] = b2bs[tjg * 5 + jj];

#pragma unroll
    for (int k = 0; k < NCLS; k++) {
        float hreg[4], w[5];
#pragma unroll
        for (int mi = 0; mi < 4; mi++) hreg[mi] = H2s[(tmg * 4 + mi) * NCLS + k];
#pragma unroll
        for (int jj = 0; jj < 5; jj++) w[jj] = W2bs[k * NCLS + tjg * 5 + jj];
#pragma unroll
        for (int mi = 0; mi < 4; mi++)
#pragma unroll
            for (int jj = 0; jj < 5; jj++)
                acc[mi][jj] = fmaf(hreg[mi], w[jj], acc[mi][jj]);
    }
#pragma unroll
    for (int mi = 0; mi < 4; mi++)
#pragma unroll
        for (int jj = 0; jj < 5; jj++)
            Os[(tmg * 4 + mi) * NCLS + tjg * 5 + jj] = acc[mi][jj];
    __syncthreads();

    // softmax stats
    if (tid < 128) {
        float mx = -INFINITY;
#pragma unroll
        for (int c = 0; c < NCLS; c++) mx = fmaxf(mx, Os[tid * NCLS + c]);
        float s = 0.f;
#pragma unroll
        for (int c = 0; c < NCLS; c++) s += __expf(Os[tid * NCLS + c] - mx);
        rmax[tid] = mx;
        rinv[tid] = 1.f / s;
    }
    __syncthreads();

    // normalized store
#pragma unroll
    for (int h = 0; h < 20; h++) {
        int e = tid + 256 * h;
        if (e < lim) {
            int m = e / NCLS;
            out[(size_t)m0 * NCLS + e] = __expf(Os[e] - rmax[m]) * rinv[m];
        }
    }
}

// ---------------------------------------------------------------------------
extern "C" void kernel_launch(void* const* d_in, const int* in_sizes, int n_in,
                              void* d_out, int out_size)
{
    const float* x   = 0; const int* edge = 0;
    const float* W1a = 0; const float* b1a = 0;
    const float* W1b = 0; const float* b1b = 0;
    const float* W2a = 0; const float* b2a = 0;
    const float* W2b = 0; const float* b2b = 0;
    int x_elems = 0, e_elems = 0;

    for (int i = 0; i < n_in; i++) {
        int sz = in_sizes[i];
        const void* p = d_in[i];
        if (sz >= 1000000 && sz % DIM == 0 && sz / DIM >= 50000) {
            if (!x) { x = (const float*)p; x_elems = sz; }
            else    { edge = (const int*)p; e_elems = sz; }
        } else if (sz >= 1000000) {
            edge = (const int*)p; e_elems = sz;
        } else if (sz == DIM * DIM) {
            if (!W1a) W1a = (const float*)p; else W1b = (const float*)p;
        } else if (sz == DIM) {
            if (!b1a) b1a = (const float*)p; else b1b = (const float*)p;
        } else if (sz == DIM * NCLS) {
            W2a = (const float*)p;
        } else if (sz == NCLS * NCLS) {
            W2b = (const float*)p;
        } else if (sz == NCLS) {
            if (!b2a) b2a = (const float*)p; else b2b = (const float*)p;
        }
    }
    if (x && edge && e_elems > x_elems) {
        const void* tx = x; x = (const float*)edge; edge = (const int*)tx;
        int t = x_elems; x_elems = e_elems; e_elems = t;
    }

    // real device addresses (NOT the host shadows)
    float *agg_p = 0, *h_p = 0, *x1_p = 0;
    cudaGetSymbolAddress((void**)&agg_p, g_agg);
    cudaGetSymbolAddress((void**)&h_p,   g_h);
    cudaGetSymbolAddress((void**)&x1_p,  g_x1);

    float* out = (float*)d_out;
    const int M = x_elems / DIM;              // 100000
    const int E = e_elems / 2;                // 1600000

    const int n4 = M * (DIM / 4);
    const int copy_blocks  = (n4 + 255) / 256;
    const int scat_blocks  = (E + 7) / 8;
    const int scat40_blk   = (E * 10 + 255) / 256;
    const int gemm_blocks  = (M + 127) / 128;

    // layer 1 (128-dim scatter)
    init_agg<<<copy_blocks, 256>>>(agg_p, x, n4);
    scatter_edges<<<scat_blocks, 256>>>(agg_p, x, edge, E);
    sgemm128<<<gemm_blocks, 256>>>(agg_p, W1a, b1a, h_p, M);
    sgemm128<<<gemm_blocks, 256>>>(h_p, W1b, b1b, x1_p, M);

    // layer 2 (project to 40 dims first, scatter in 40-dim space)
    // y40 reuses g_h, agg40 reuses g_agg (both dead after layer 1)
    gemm_y40<<<gemm_blocks, 256>>>(x1_p, W2a, h_p, agg_p, M);
    scatter40<<<scat40_blk, 256>>>(agg_p, h_p, edge, E);
    head40<<<gemm_blocks, 256>>>(agg_p, b2a, W2b, b2b, out, M);
}